// round 10
// baseline (speedup 1.0000x reference)
#include <cuda_runtime.h>
#include <cuda_bf16.h>
#include <math.h>
#include <stdint.h>

// GaussianScorer sm_103a: warp-specialized bf16 mma.sync pipeline.
//  8 consumer warps (LDSM+MMA only, 64x32 warp tiles) + 4 producer warps
//  (LDG A fp32 -> e2 -> cvt -> STS bf16; cp.async B), mbarrier-decoupled.
// out[m,l] = logc - 0.5*e2[m] - 0.5*m2[l] + cross[m,l]
// Shapes: M=16384, L=128, K=512.  BM=128, BK=64, 4-stage ring, grid=128.

#define GS_M 16384
#define GS_K 512
#define GS_L 128
#define BM   128
#define BKT  64
#define NITER (GS_K / BKT)   // 8
#define NSTG 4
#define NTHREADS 384         // 256 consumers + 128 producers

#define A_STAGE 16384        // 128 rows * 128B (64 bf16)
#define B_STAGE 16384
#define IV_OFF   128         // 512 f32
#define MOFF_OFF 2176        // 128 f32
#define E2_OFF   2688        // 128 f32
#define A_OFF    4096
#define B_OFF    (A_OFF + NSTG * A_STAGE)      // 69632
#define SMEM_TOTAL (B_OFF + NSTG * B_STAGE)    // 135168

__device__ __nv_bfloat16 g_Bh[GS_L * GS_K];
__device__ float g_m2[GS_L];
__device__ float g_logc;

static __device__ __forceinline__ uint32_t smem_u32(const void* p) {
    uint32_t a;
    asm("{ .reg .u64 t; cvta.to.shared.u64 t, %1; cvt.u32.u64 %0, t; }" : "=r"(a) : "l"(p));
    return a;
}

#define MBAR_INIT(a, c) asm volatile("mbarrier.init.shared.b64 [%0], %1;" :: "r"(a), "r"(c) : "memory")
#define MBAR_ARRIVE(a)  asm volatile("mbarrier.arrive.shared.b64 _, [%0];" :: "r"(a) : "memory")
#define MBAR_WAIT(a, ph) do {                                                    \
    uint32_t _m = (a), _p = (ph), _d;                                            \
    asm volatile("{ .reg .pred p;"                                               \
        " mbarrier.try_wait.parity.acquire.cta.shared::cta.b64 p, [%1], %2;"     \
        " selp.b32 %0, 1, 0, p; }" : "=r"(_d) : "r"(_m), "r"(_p) : "memory");    \
    if (!_d) {                                                                   \
        asm volatile("{ .reg .pred P1;"                                          \
            " WL_%=:"                                                            \
            " mbarrier.try_wait.parity.acquire.cta.shared::cta.b64 P1, [%0], %1, 0x989680;" \
            " @P1 bra.uni WD_%=;"                                                \
            " bra.uni WL_%=;"                                                    \
            " WD_%=: }" :: "r"(_m), "r"(_p) : "memory");                         \
    }                                                                            \
} while (0)
#define CP_ASYNC16(dst, src) \
    asm volatile("cp.async.cg.shared.global [%0], [%1], 16;" :: "r"(dst), "l"(src) : "memory")
#define CP_MBAR_ARRIVE(a) \
    asm volatile("cp.async.mbarrier.arrive.noinc.shared::cta.b64 [%0];" :: "r"(a) : "memory")

#define LDSM_X4(r, addr)                                                        \
    asm volatile("ldmatrix.sync.aligned.m8n8.x4.shared.b16 {%0,%1,%2,%3}, [%4];" \
        : "=r"((r)[0]), "=r"((r)[1]), "=r"((r)[2]), "=r"((r)[3]) : "r"(addr))

#define MMA_BF16(d, a, b0, b1)                                                  \
    asm volatile("mma.sync.aligned.m16n8k16.row.col.f32.bf16.bf16.f32 "         \
        "{%0,%1,%2,%3}, {%4,%5,%6,%7}, {%8,%9}, {%0,%1,%2,%3};"                 \
        : "+f"((d)[0]), "+f"((d)[1]), "+f"((d)[2]), "+f"((d)[3])                \
        : "r"((a)[0]), "r"((a)[1]), "r"((a)[2]), "r"((a)[3]), "r"(b0), "r"(b1))

// 128B rows, 8 x 16B chunks, chunk ^= row&7
#define SWZ(row, chunk) ((uint32_t)((row) * 128 + (((chunk) ^ ((row) & 7)) << 4)))

// ---------------- prep: g_Bh = bf16(means*inv_var), g_m2, g_logc ----------------
__global__ void gs_prep(const float* __restrict__ means, const float* __restrict__ var) {
    __shared__ float red[4];
    const int l = blockIdx.x;
    const int t = threadIdx.x;        // 128 threads, 4 elems each
    const int i0 = t * 4;

    float4 v4 = *(const float4*)(var + i0);
    float4 m4 = *(const float4*)(means + (size_t)l * GS_K + i0);
    float4 b4 = make_float4(m4.x / v4.x, m4.y / v4.y, m4.z / v4.z, m4.w / v4.w);

    __nv_bfloat162 p0 = __floats2bfloat162_rn(b4.x, b4.y);
    __nv_bfloat162 p1 = __floats2bfloat162_rn(b4.z, b4.w);
    *(uint2*)(g_Bh + (size_t)l * GS_K + i0) =
        make_uint2(*(uint32_t*)&p0, *(uint32_t*)&p1);

    float m2 = m4.x * b4.x + m4.y * b4.y + m4.z * b4.z + m4.w * b4.w;
    #pragma unroll
    for (int o = 16; o > 0; o >>= 1) m2 += __shfl_xor_sync(0xffffffffu, m2, o);
    if ((t & 31) == 0) red[t >> 5] = m2;
    __syncthreads();
    if (t == 0) g_m2[l] = red[0] + red[1] + red[2] + red[3];

    if (l == 0) {
        __syncthreads();
        float lg = logf(v4.x) + logf(v4.y) + logf(v4.z) + logf(v4.w);
        #pragma unroll
        for (int o = 16; o > 0; o >>= 1) lg += __shfl_xor_sync(0xffffffffu, lg, o);
        if ((t & 31) == 0) red[t >> 5] = lg;
        __syncthreads();
        if (t == 0) {
            const float FACTOR = -256.0f * 1.8378770664093453f;   // -E/2 * ln(2*pi)
            g_logc = FACTOR - 0.5f * (red[0] + red[1] + red[2] + red[3]);
        }
    }
}

// ---------------- main kernel ----------------
__global__ __launch_bounds__(NTHREADS, 1)
void gs_main(const float* __restrict__ emb, const float* __restrict__ var,
             float* __restrict__ out) {
    extern __shared__ __align__(1024) char smem[];
    const uint32_t sb = smem_u32(smem);
    const int tid = threadIdx.x;
    const int m0 = blockIdx.x * BM;

    if (tid == 0) {
        #pragma unroll
        for (int s = 0; s < NSTG; s++) {
            MBAR_INIT(sb + 8 * s, 256);        // full[s]: 128 STS-arrive + 128 cp-arrive
            MBAR_INIT(sb + 32 + 8 * s, 256);   // empty[s]: 256 consumer arrives
        }
    }
    if (tid >= 256) {                          // producers also stage tables
        const int p = tid - 256;
        float4 v4 = *(const float4*)(var + p * 4);
        *(float4*)(smem + IV_OFF + p * 16) =
            make_float4(1.0f / v4.x, 1.0f / v4.y, 1.0f / v4.z, 1.0f / v4.w);
        ((float*)(smem + MOFF_OFF))[p] = g_logc - 0.5f * g_m2[p];
    }
    __syncthreads();

    float acc[4][4][4];

    if (tid >= 256) {
        // ================= producers =================
        const int prow = tid - 256;            // 0..127: owns one M-row and one B-row
        const float* aSrc = emb + (size_t)(m0 + prow) * GS_K;
        const char* bSrc = (const char*)(g_Bh + (size_t)prow * GS_K);
        const float* ivp = (const float*)(smem + IV_OFF);
        float e2p = 0.0f;

        float4 rA[16];
        #pragma unroll
        for (int q = 0; q < 16; q++) rA[q] = *(const float4*)(aSrc + q * 4);

        #pragma unroll
        for (int f = 0; f < NITER; ++f) {
            const int s = f & (NSTG - 1);
            const int kt = f * BKT;
            if (f >= NSTG) MBAR_WAIT(sb + 32 + 8 * s, 0);

            // exact fp32 e2 + convert to bf16 chunks
            uint4 cc[8];
            #pragma unroll
            for (int q = 0; q < 8; q++) {
                float4 x0 = rA[2 * q], x1 = rA[2 * q + 1];
                float4 v0 = *(const float4*)(ivp + kt + 8 * q);
                float4 v1 = *(const float4*)(ivp + kt + 8 * q + 4);
                e2p = fmaf(x0.x * x0.x, v0.x, e2p);
                e2p = fmaf(x0.y * x0.y, v0.y, e2p);
                e2p = fmaf(x0.z * x0.z, v0.z, e2p);
                e2p = fmaf(x0.w * x0.w, v0.w, e2p);
                e2p = fmaf(x1.x * x1.x, v1.x, e2p);
                e2p = fmaf(x1.y * x1.y, v1.y, e2p);
                e2p = fmaf(x1.z * x1.z, v1.z, e2p);
                e2p = fmaf(x1.w * x1.w, v1.w, e2p);
                __nv_bfloat162 b0 = __floats2bfloat162_rn(x0.x, x0.y);
                __nv_bfloat162 b1 = __floats2bfloat162_rn(x0.z, x0.w);
                __nv_bfloat162 b2 = __floats2bfloat162_rn(x1.x, x1.y);
                __nv_bfloat162 b3 = __floats2bfloat162_rn(x1.z, x1.w);
                cc[q] = make_uint4(*(uint32_t*)&b0, *(uint32_t*)&b1,
                                   *(uint32_t*)&b2, *(uint32_t*)&b3);
            }

            // prefetch next A slice while this stage's STS/cp.async retire
            if (f + 1 < NITER) {
                #pragma unroll
                for (int q = 0; q < 16; q++)
                    rA[q] = *(const float4*)(aSrc + kt + BKT + q * 4);
            }

            #pragma unroll
            for (int c = 0; c < 8; c++)
                *(uint4*)(smem + A_OFF + s * A_STAGE + SWZ(prow, c)) = cc[c];

            const uint32_t bb = sb + B_OFF + s * B_STAGE;
            #pragma unroll
            for (int c = 0; c < 8; c++)
                CP_ASYNC16(bb + SWZ(prow, c), bSrc + (kt + c * 8) * 2);
            CP_MBAR_ARRIVE(sb + 8 * s);
            MBAR_ARRIVE(sb + 8 * s);
        }
        ((float*)(smem + E2_OFF))[prow] = e2p;
    } else {
        // ================= consumers: pure LDSM + MMA =================
        const int lane = tid & 31;
        const int mm = lane >> 3;
        const int mrow = lane & 7;
        const int cw = tid >> 5;           // 0..7
        const int wm = cw >> 2;            // 0..1 -> 64 rows
        const int wn = cw & 3;             // 0..3 -> 32 cols

        const int rowAb = wm * 64 + (mm & 1) * 8 + mrow;
        const int rowBb = wn * 32 + (mm >> 1) * 8 + mrow;
        const int cA = mm >> 1;
        const int cB = mm & 1;

        #pragma unroll
        for (int mt = 0; mt < 4; mt++)
            #pragma unroll
            for (int nt = 0; nt < 4; nt++)
                #pragma unroll
                for (int j = 0; j < 4; j++) acc[mt][nt][j] = 0.0f;

        #pragma unroll
        for (int it = 0; it < NITER; ++it) {
            const int s = it & (NSTG - 1);
            MBAR_WAIT(sb + 8 * s, (it >> 2) & 1);
            const uint32_t As = sb + A_OFF + s * A_STAGE;
            const uint32_t Bs = sb + B_OFF + s * B_STAGE;

            #pragma unroll
            for (int ks = 0; ks < 4; ks++) {
                const int c0 = ks * 2;
                uint32_t af[4][4], bq[2][4];
                LDSM_X4(af[0], As + SWZ(rowAb,      c0 + cA));
                LDSM_X4(af[1], As + SWZ(rowAb + 16, c0 + cA));
                LDSM_X4(af[2], As + SWZ(rowAb + 32, c0 + cA));
                LDSM_X4(af[3], As + SWZ(rowAb + 48, c0 + cA));
                LDSM_X4(bq[0], Bs + SWZ(rowBb,      c0 + cB));
                LDSM_X4(bq[1], Bs + SWZ(rowBb + 16, c0 + cB));
                #pragma unroll
                for (int mt = 0; mt < 4; mt++) {
                    MMA_BF16(acc[mt][0], af[mt], bq[0][0], bq[0][1]);
                    MMA_BF16(acc[mt][1], af[mt], bq[0][2], bq[0][3]);
                    MMA_BF16(acc[mt][2], af[mt], bq[1][0], bq[1][1]);
                    MMA_BF16(acc[mt][3], af[mt], bq[1][2], bq[1][3]);
                }
            }
            MBAR_ARRIVE(sb + 32 + 8 * s);
        }
    }

    __syncthreads();   // e2 published; producers done

    if (tid < 256) {
        const int lane = tid & 31;
        const int g = lane >> 2;
        const int tig = lane & 3;
        const int cw = tid >> 5;
        const int wm = cw >> 2;
        const int wn = cw & 3;
        const float* sE2 = (const float*)(smem + E2_OFF);
        const float* moff = (const float*)(smem + MOFF_OFF);

        #pragma unroll
        for (int mt = 0; mt < 4; mt++) {
            const int r0 = wm * 64 + mt * 16 + g;
            const float rb0 = -0.5f * sE2[r0];
            const float rb1 = -0.5f * sE2[r0 + 8];
            float* orow0 = out + (size_t)(m0 + r0) * GS_L;
            float* orow1 = orow0 + 8 * GS_L;
            #pragma unroll
            for (int nt = 0; nt < 4; nt++) {
                const int col = wn * 32 + nt * 8 + tig * 2;
                float2 mo = *(const float2*)(moff + col);
                float2 o0, o1;
                o0.x = acc[mt][nt][0] + rb0 + mo.x;
                o0.y = acc[mt][nt][1] + rb0 + mo.y;
                o1.x = acc[mt][nt][2] + rb1 + mo.x;
                o1.y = acc[mt][nt][3] + rb1 + mo.y;
                *(float2*)(orow0 + col) = o0;
                *(float2*)(orow1 + col) = o1;
            }
        }
    }
}

extern "C" void kernel_launch(void* const* d_in, const int* in_sizes, int n_in,
                              void* d_out, int out_size) {
    const float* emb   = (const float*)d_in[0];   // [8, 2048, 512] f32
    const float* means = (const float*)d_in[1];   // [128, 512] f32
    const float* var   = (const float*)d_in[2];   // [512] f32
    float* out = (float*)d_out;                   // [8, 2048, 128] f32
    (void)in_sizes; (void)n_in; (void)out_size;

    cudaFuncSetAttribute(gs_main, cudaFuncAttributeMaxDynamicSharedMemorySize, SMEM_TOTAL);
    gs_prep<<<GS_L, 128>>>(means, var);
    gs_main<<<GS_M / BM, NTHREADS, SMEM_TOTAL>>>(emb, var, out);
}